// round 5
// baseline (speedup 1.0000x reference)
#include <cuda_runtime.h>

#define W 512
#define H 512
#define BATCH 2
#define HW (H*W)
#define NCV (BATCH*(H-1)*W)
#define NCH (BATCH*H*(W-1))
#define L_STEP 0.24f
#define KK 0.0009f   /* 0.03*0.03 */

#define TW 128
#define TH 64
#define HALO 8
#define TSX (TW - 2*HALO)   /* 112 interior width  */
#define TSY (TH - 2*HALO)   /* 48  interior height */
#define NBX 5               /* ceil(512/112) */
#define NBY 11              /* ceil(512/48)  */
#define NTI 32              /* thread-columns (x) == lane id */
#define NTJ 16              /* thread-rows (y)    == warp id */
#define NTHREADS (NTI*NTJ)
#define NCTAS (NBX*NBY*BATCH)   /* 110 <= 148 SMs: co-resident, grid barrier safe */
#define NPH 63                  /* 62*8 + 4 = 500 steps */

/* scratch state (ping-pong) + premultiplied conductances + barrier flags */
__device__ float g_I0[BATCH*HW];
__device__ float g_I1[BATCH*HW];
__device__ float g_cvL[NCV];
__device__ float g_chL[NCH];
__device__ unsigned g_flags[NCTAS];

/* ---- conductance kernels: raw g to d_out region, L*g to scratch ---- */
__global__ void k_coeff_v(const float* __restrict__ guide, float* __restrict__ out_cv) {
    int idx = blockIdx.x*blockDim.x + threadIdx.x;
    if (idx >= NCV) return;
    int x = idx % W;
    int y = (idx / W) % (H-1);
    int b = idx / (W*(H-1));
    const float* gb = guide + (size_t)b*3*HW + (size_t)y*W + x;
    float s = 0.f;
    #pragma unroll
    for (int c = 0; c < 3; c++) s += fabsf(gb[(size_t)c*HW + W] - gb[(size_t)c*HW]);
    float m = s * (1.0f/3.0f);
    float g = 1.0f / (1.0f + (m*m)/KK);
    out_cv[idx] = g;
    g_cvL[idx]  = L_STEP * g;
}

__global__ void k_coeff_h(const float* __restrict__ guide, float* __restrict__ out_ch) {
    int idx = blockIdx.x*blockDim.x + threadIdx.x;
    if (idx >= NCH) return;
    int x = idx % (W-1);
    int y = (idx / (W-1)) % H;
    int b = idx / ((W-1)*H);
    const float* gb = guide + (size_t)b*3*HW + (size_t)y*W + x;
    float s = 0.f;
    #pragma unroll
    for (int c = 0; c < 3; c++) s += fabsf(gb[(size_t)c*HW + 1] - gb[(size_t)c*HW]);
    float m = s * (1.0f/3.0f);
    float g = 1.0f / (1.0f + (m*m)/KK);
    out_ch[idx] = g;
    g_chL[idx]  = L_STEP * g;
}

__global__ void k_reset() {
    int idx = threadIdx.x;
    if (idx < NCTAS) g_flags[idx] = 0u;
}

/* ---- gmem flag ops for the inter-CTA barrier ---- */
__device__ __forceinline__ void flag_store_release(unsigned* p, unsigned v) {
    asm volatile("st.release.gpu.u32 [%0], %1;" :: "l"(p), "r"(v) : "memory");
}
__device__ __forceinline__ unsigned flag_load_acquire(const unsigned* p) {
    unsigned v;
    asm volatile("ld.acquire.gpu.u32 %0, [%1];" : "=r"(v) : "l"(p) : "memory");
    return v;
}

/* ---- smem flag ops for neighbor-warp sync ---- */
__device__ __forceinline__ void sflag_store_release(unsigned* p, unsigned v) {
    unsigned a = (unsigned)__cvta_generic_to_shared(p);
    asm volatile("st.release.cta.shared::cta.u32 [%0], %1;" :: "r"(a), "r"(v) : "memory");
}
__device__ __forceinline__ unsigned sflag_load_acquire(const unsigned* p) {
    unsigned a = (unsigned)__cvta_generic_to_shared(p);
    unsigned v;
    asm volatile("ld.acquire.cta.shared::cta.u32 %0, [%1];" : "=r"(v) : "r"(a) : "memory");
    return v;
}

/* software grid barrier: all NCTAS CTAs co-resident (1 CTA/SM, 110<=148). */
__device__ __forceinline__ void grid_barrier(int cta, unsigned target) {
    __syncthreads();
    if (threadIdx.x == 0) flag_store_release(&g_flags[cta], target);
    if (threadIdx.x < NCTAS) {
        while (flag_load_acquire(&g_flags[threadIdx.x]) < target) { __nanosleep(32); }
    }
    __syncthreads();
}

/* ---- persistent temporal-blocked diffusion ----
 * Thread-private 4x4 register block; coefficients register-resident for all
 * 500 steps. Per step: top/bottom rows exchanged with the two neighbor warps
 * via double-buffered smem guarded by per-warp monotone step flags
 * (release/acquire + __syncwarp) -- NO CTA-wide barrier inside a phase.
 * Protocol safety: publish(g) -> wait(nb>=g) -> read -> compute. Seeing
 * nb flag >= g implies nb finished reading step g-1 buffers, so the 2-deep
 * buffer ring is never overwritten while in use, and my flag g+1 is only
 * published after my reads of step-g data complete. Left/right via warp
 * shuffles (in-warp, sync-free). Every 8 steps: interior write, grid
 * barrier, reload. */
__global__ void __launch_bounds__(NTHREADS, 1)
k_persist(const float* __restrict__ initial, float* __restrict__ out_y) {
    __shared__ float sTop[2][NTJ][TW];
    __shared__ float sBot[2][NTJ][TW];
    __shared__ unsigned sFlag[NTJ];

    const int tid = threadIdx.x;
    const int ti  = tid & 31;          /* lane id  = x thread-column */
    const int tj  = tid >> 5;          /* warp id  = y thread-row    */
    const int bx = blockIdx.x, by = blockIdx.y, b = blockIdx.z;
    const int cta = bx + NBX*(by + NBY*b);

    const int ox  = bx*TSX - HALO;
    const int oy  = by*TSY - HALO;
    const int lx0 = ti*4, ly0 = tj*4;
    const int gx0 = ox + lx0;
    const int gy0 = oy + ly0;
    const bool xok = (gx0 >= 0) && (gx0 + 4 <= W);

    if (tid < NTJ) sFlag[tid] = 0u;

    const float* __restrict__ cvb = g_cvL + (size_t)b*(H-1)*W;
    const float* __restrict__ chb = g_chL + (size_t)b*H*(W-1);

    /* persistent coefficient registers */
    float CV[5][4];   /* rows gy0-1 .. gy0+3 of L*cv */
    #pragma unroll
    for (int jj = 0; jj < 5; jj++) {
        int r = gy0 - 1 + jj;
        if (xok && r >= 0 && r < H-1) {
            float4 v = *(const float4*)(cvb + (size_t)r*W + gx0);
            CV[jj][0]=v.x; CV[jj][1]=v.y; CV[jj][2]=v.z; CV[jj][3]=v.w;
        } else {
            CV[jj][0]=0.f; CV[jj][1]=0.f; CV[jj][2]=0.f; CV[jj][3]=0.f;
        }
    }
    float CH[4][5];   /* cols gx0-1 .. gx0+3 of L*ch */
    #pragma unroll
    for (int j = 0; j < 4; j++) {
        int gy = gy0 + j;
        #pragma unroll
        for (int ii = 0; ii < 5; ii++) {
            int c = gx0 - 1 + ii;
            CH[j][ii] = (gy >= 0 && gy < H && c >= 0 && c < W-1)
                      ? chb[(size_t)gy*(W-1) + c] : 0.f;
        }
    }

    /* initial state straight from input */
    float I[4][4];
    {
        const float* __restrict__ srcb = initial + (size_t)b*HW;
        #pragma unroll
        for (int j = 0; j < 4; j++) {
            int gy = gy0 + j;
            if (xok && gy >= 0 && gy < H) {
                float4 v = *(const float4*)(srcb + (size_t)gy*W + gx0);
                I[j][0]=v.x; I[j][1]=v.y; I[j][2]=v.z; I[j][3]=v.w;
            } else {
                I[j][0]=0.f; I[j][1]=0.f; I[j][2]=0.f; I[j][3]=0.f;
            }
        }
    }
    __syncthreads();   /* sFlag init + coeff loads visible before mainloop */

    unsigned gstep = 0;   /* cumulative step counter, never reset */

    for (int p = 0; p < NPH; p++) {
        const int nsteps = (p == NPH-1) ? 4 : HALO;
        for (int s = 0; s < nsteps; s++) {
            const int bs = (int)(gstep & 1u);
            /* publish top/bottom rows (pre-update values) */
            *(float4*)&sTop[bs][tj][lx0] = make_float4(I[0][0],I[0][1],I[0][2],I[0][3]);
            *(float4*)&sBot[bs][tj][lx0] = make_float4(I[3][0],I[3][1],I[3][2],I[3][3]);
            __syncwarp();                      /* order all lanes' STS before flag */
            if (ti == 0) sflag_store_release(&sFlag[tj], gstep + 1u);

            /* left/right neighbors via shuffles (pre-update values) */
            float lf[4], rt[4];
            #pragma unroll
            for (int j = 0; j < 4; j++) {
                lf[j] = __shfl_up_sync  (0xffffffffu, I[j][3], 1);
                rt[j] = __shfl_down_sync(0xffffffffu, I[j][0], 1);
            }

            /* wait for neighbor warps to publish step gstep */
            const unsigned need = gstep + 1u;
            if (tj > 0)     { while (sflag_load_acquire(&sFlag[tj-1]) < need) { } }
            if (tj < NTJ-1) { while (sflag_load_acquire(&sFlag[tj+1]) < need) { } }

            float4 upv = (tj > 0)     ? *(float4*)&sBot[bs][tj-1][lx0] : make_float4(0,0,0,0);
            float4 dnv = (tj < NTJ-1) ? *(float4*)&sTop[bs][tj+1][lx0] : make_float4(0,0,0,0);
            float up[4] = {upv.x, upv.y, upv.z, upv.w};
            float dn[4] = {dnv.x, dnv.y, dnv.z, dnv.w};

            float N_[4][4];
            /* vertical: N = (I - tv_up) + tv_down */
            #pragma unroll
            for (int i = 0; i < 4; i++) {
                float f0 = CV[0][i] * (I[0][i] - up[i]);
                float f1 = CV[1][i] * (I[1][i] - I[0][i]);
                float f2 = CV[2][i] * (I[2][i] - I[1][i]);
                float f3 = CV[3][i] * (I[3][i] - I[2][i]);
                float f4 = CV[4][i] * (dn[i]   - I[3][i]);
                N_[0][i] = (I[0][i] - f0) + f1;
                N_[1][i] = (I[1][i] - f1) + f2;
                N_[2][i] = (I[2][i] - f2) + f3;
                N_[3][i] = (I[3][i] - f3) + f4;
            }
            /* horizontal (dh from pre-update I): I = (N - th_l) + th_r */
            #pragma unroll
            for (int j = 0; j < 4; j++) {
                float g0 = CH[j][0] * (I[j][0] - lf[j]);
                float g1 = CH[j][1] * (I[j][1] - I[j][0]);
                float g2 = CH[j][2] * (I[j][2] - I[j][1]);
                float g3 = CH[j][3] * (I[j][3] - I[j][2]);
                float g4 = CH[j][4] * (rt[j]   - I[j][3]);
                I[j][0] = (N_[j][0] - g0) + g1;
                I[j][1] = (N_[j][1] - g1) + g2;
                I[j][2] = (N_[j][2] - g2) + g3;
                I[j][3] = (N_[j][3] - g3) + g4;
            }
            gstep++;
        }

        /* write interior: last phase straight to output, else ping-pong */
        float* __restrict__ wb = (p == NPH-1)
            ? (out_y + (size_t)b*HW)
            : (((p & 1) ? g_I0 : g_I1) + (size_t)b*HW);
        if (xok && lx0 >= HALO && lx0 < TW - HALO) {
            #pragma unroll
            for (int j = 0; j < 4; j++) {
                int ly = ly0 + j;
                int gy = gy0 + j;
                if (ly >= HALO && ly < TH - HALO && gy < H) {
                    *(float4*)(wb + (size_t)gy*W + gx0) =
                        make_float4(I[j][0], I[j][1], I[j][2], I[j][3]);
                }
            }
        }

        if (p < NPH-1) {
            grid_barrier(cta, (unsigned)(p + 1));
            const float* __restrict__ rb = ((p & 1) ? g_I0 : g_I1) + (size_t)b*HW;
            #pragma unroll
            for (int j = 0; j < 4; j++) {
                int gy = gy0 + j;
                if (xok && gy >= 0 && gy < H) {
                    float4 v = *(const float4*)(rb + (size_t)gy*W + gx0);
                    I[j][0]=v.x; I[j][1]=v.y; I[j][2]=v.z; I[j][3]=v.w;
                } else {
                    I[j][0]=0.f; I[j][1]=0.f; I[j][2]=0.f; I[j][3]=0.f;
                }
            }
        }
    }
}

extern "C" void kernel_launch(void* const* d_in, const int* in_sizes, int n_in,
                              void* d_out, int out_size) {
    const float* a0 = (const float*)d_in[0];
    const float* a1 = (const float*)d_in[1];
    const float* guide = a0;
    const float* initial = a1;
    if (n_in >= 2 && in_sizes[0] < in_sizes[1]) { guide = a1; initial = a0; }

    float* out    = (float*)d_out;
    float* out_y  = out;                       /* [BATCH*HW]   */
    float* out_cv = out + BATCH*HW;            /* [NCV]        */
    float* out_ch = out_cv + NCV;              /* [NCH]        */

    k_reset<<<1, 128>>>();
    k_coeff_v<<<(NCV + 255)/256, 256>>>(guide, out_cv);
    k_coeff_h<<<(NCH + 255)/256, 256>>>(guide, out_ch);

    dim3 grid(NBX, NBY, BATCH);
    k_persist<<<grid, NTHREADS>>>(initial, out_y);
}

// round 6
// speedup vs baseline: 2.2064x; 2.2064x over previous
#include <cuda_runtime.h>

#define W 512
#define H 512
#define BATCH 2
#define HW (H*W)
#define NCV (BATCH*(H-1)*W)
#define NCH (BATCH*H*(W-1))
#define L_STEP 0.24f
#define KK 0.0009f   /* 0.03*0.03 */

#define TW 128
#define TH 64
#define HALO 12
#define TSX (TW - 2*HALO)   /* 104 interior width  */
#define TSY (TH - 2*HALO)   /* 40  interior height */
#define NBX 5               /* ceil(512/104) */
#define NBY 13              /* ceil(512/40)  */
#define NTI 32              /* thread-columns (x) == lane id */
#define NTJ 16              /* thread-rows (y)    == warp id */
#define NTHREADS (NTI*NTJ)
#define NCTAS (NBX*NBY*BATCH)   /* 130 <= 148 SMs: co-resident, grid barrier safe */
#define NPH 42                  /* 41*12 + 8 = 500 steps */
#define FLAG_STRIDE 32          /* 128B apart: no same-line write serialization */

/* scratch state (ping-pong) + premultiplied conductances + barrier flags */
__device__ float g_I0[BATCH*HW];
__device__ float g_I1[BATCH*HW];
__device__ float g_cvL[NCV];
__device__ float g_chL[NCH];
__device__ unsigned g_flags[NCTAS*FLAG_STRIDE];

/* ---- conductance kernels: raw g to d_out region, L*g to scratch ---- */
__global__ void k_coeff_v(const float* __restrict__ guide, float* __restrict__ out_cv) {
    int idx = blockIdx.x*blockDim.x + threadIdx.x;
    if (idx >= NCV) return;
    int x = idx % W;
    int y = (idx / W) % (H-1);
    int b = idx / (W*(H-1));
    const float* gb = guide + (size_t)b*3*HW + (size_t)y*W + x;
    float s = 0.f;
    #pragma unroll
    for (int c = 0; c < 3; c++) s += fabsf(gb[(size_t)c*HW + W] - gb[(size_t)c*HW]);
    float m = s * (1.0f/3.0f);
    float g = 1.0f / (1.0f + (m*m)/KK);
    out_cv[idx] = g;
    g_cvL[idx]  = L_STEP * g;
}

__global__ void k_coeff_h(const float* __restrict__ guide, float* __restrict__ out_ch) {
    int idx = blockIdx.x*blockDim.x + threadIdx.x;
    if (idx >= NCH) return;
    int x = idx % (W-1);
    int y = (idx / (W-1)) % H;
    int b = idx / ((W-1)*H);
    const float* gb = guide + (size_t)b*3*HW + (size_t)y*W + x;
    float s = 0.f;
    #pragma unroll
    for (int c = 0; c < 3; c++) s += fabsf(gb[(size_t)c*HW + 1] - gb[(size_t)c*HW]);
    float m = s * (1.0f/3.0f);
    float g = 1.0f / (1.0f + (m*m)/KK);
    out_ch[idx] = g;
    g_chL[idx]  = L_STEP * g;
}

__global__ void k_reset() {
    int idx = blockIdx.x*blockDim.x + threadIdx.x;
    if (idx < NCTAS) g_flags[idx*FLAG_STRIDE] = 0u;
}

__device__ __forceinline__ void flag_store_release(unsigned* p, unsigned v) {
    asm volatile("st.release.gpu.u32 [%0], %1;" :: "l"(p), "r"(v) : "memory");
}
__device__ __forceinline__ unsigned flag_load_acquire(const unsigned* p) {
    unsigned v;
    asm volatile("ld.acquire.gpu.u32 %0, [%1];" : "=r"(v) : "l"(p) : "memory");
    return v;
}

/* software grid barrier: all NCTAS CTAs co-resident (1 CTA/SM, 130<=148). */
__device__ __forceinline__ void grid_barrier(int cta, unsigned target) {
    __syncthreads();
    if (threadIdx.x == 0) flag_store_release(&g_flags[cta*FLAG_STRIDE], target);
    if (threadIdx.x < NCTAS) {
        while (flag_load_acquire(&g_flags[threadIdx.x*FLAG_STRIDE]) < target) {
            __nanosleep(32);
        }
    }
    __syncthreads();
}

/* ---- persistent temporal-blocked diffusion ----
 * Thread-private 4x4 register block; coefficients register-resident for all
 * 500 steps. Per step the horizontal fluxes and interior vertical fluxes are
 * computed BEFORE the CTA barrier (they depend only on pre-update I); only
 * f0/f4 (needing up/dn rows) and the combines run after it. Identical ops &
 * rounding to the validated kernel, just reordered across independent values.
 * Every 12 steps: interior write, grid barrier, reload (halo threads only). */
__global__ void __launch_bounds__(NTHREADS, 1)
k_persist(const float* __restrict__ initial, float* __restrict__ out_y) {
    __shared__ float sTop[2][NTJ][TW];
    __shared__ float sBot[2][NTJ][TW];

    const int tid = threadIdx.x;
    const int ti  = tid & 31;          /* lane id  = x thread-column */
    const int tj  = tid >> 5;          /* warp id  = y thread-row    */
    const int bx = blockIdx.x, by = blockIdx.y, b = blockIdx.z;
    const int cta = bx + NBX*(by + NBY*b);

    const int ox  = bx*TSX - HALO;
    const int oy  = by*TSY - HALO;
    const int lx0 = ti*4, ly0 = tj*4;
    const int gx0 = ox + lx0;
    const int gy0 = oy + ly0;
    const bool xok = (gx0 >= 0) && (gx0 + 4 <= W);
    /* thread's 4x4 fully inside the garbage-free tile interior after a full
     * phase -> its registers equal the canonical buffer: skip reload */
    const bool skipReload = (lx0 >= HALO) && (lx0 + 4 <= TW - HALO) &&
                            (ly0 >= HALO) && (ly0 + 4 <= TH - HALO);

    const float* __restrict__ cvb = g_cvL + (size_t)b*(H-1)*W;
    const float* __restrict__ chb = g_chL + (size_t)b*H*(W-1);

    /* persistent coefficient registers */
    float CV[5][4];   /* rows gy0-1 .. gy0+3 of L*cv */
    #pragma unroll
    for (int jj = 0; jj < 5; jj++) {
        int r = gy0 - 1 + jj;
        if (xok && r >= 0 && r < H-1) {
            float4 v = *(const float4*)(cvb + (size_t)r*W + gx0);
            CV[jj][0]=v.x; CV[jj][1]=v.y; CV[jj][2]=v.z; CV[jj][3]=v.w;
        } else {
            CV[jj][0]=0.f; CV[jj][1]=0.f; CV[jj][2]=0.f; CV[jj][3]=0.f;
        }
    }
    float CH[4][5];   /* cols gx0-1 .. gx0+3 of L*ch */
    #pragma unroll
    for (int j = 0; j < 4; j++) {
        int gy = gy0 + j;
        #pragma unroll
        for (int ii = 0; ii < 5; ii++) {
            int c = gx0 - 1 + ii;
            CH[j][ii] = (gy >= 0 && gy < H && c >= 0 && c < W-1)
                      ? chb[(size_t)gy*(W-1) + c] : 0.f;
        }
    }

    /* initial state straight from input */
    float I[4][4];
    {
        const float* __restrict__ srcb = initial + (size_t)b*HW;
        #pragma unroll
        for (int j = 0; j < 4; j++) {
            int gy = gy0 + j;
            if (xok && gy >= 0 && gy < H) {
                float4 v = *(const float4*)(srcb + (size_t)gy*W + gx0);
                I[j][0]=v.x; I[j][1]=v.y; I[j][2]=v.z; I[j][3]=v.w;
            } else {
                I[j][0]=0.f; I[j][1]=0.f; I[j][2]=0.f; I[j][3]=0.f;
            }
        }
    }

    for (int p = 0; p < NPH; p++) {
        const int nsteps = (p == NPH-1) ? (500 - (NPH-1)*HALO) : HALO;
        for (int s = 0; s < nsteps; s++) {
            const int bs = s & 1;

            /* --- pre-barrier: everything that needs only pre-update I --- */
            float lf[4], rt[4];
            #pragma unroll
            for (int j = 0; j < 4; j++) {
                lf[j] = __shfl_up_sync  (0xffffffffu, I[j][3], 1);  /* lane0 garbage -> zero coeff */
                rt[j] = __shfl_down_sync(0xffffffffu, I[j][0], 1);  /* lane31 garbage -> zero coeff */
            }
            /* horizontal fluxes, all 5 per row */
            float G[4][5];
            #pragma unroll
            for (int j = 0; j < 4; j++) {
                G[j][0] = CH[j][0] * (I[j][0] - lf[j]);
                G[j][1] = CH[j][1] * (I[j][1] - I[j][0]);
                G[j][2] = CH[j][2] * (I[j][2] - I[j][1]);
                G[j][3] = CH[j][3] * (I[j][3] - I[j][2]);
                G[j][4] = CH[j][4] * (rt[j]   - I[j][3]);
            }
            /* interior vertical fluxes f1..f3 */
            float F1[4], F2[4], F3[4];
            #pragma unroll
            for (int i = 0; i < 4; i++) {
                F1[i] = CV[1][i] * (I[1][i] - I[0][i]);
                F2[i] = CV[2][i] * (I[2][i] - I[1][i]);
                F3[i] = CV[3][i] * (I[3][i] - I[2][i]);
            }
            /* publish top/bottom rows (pre-update values) */
            *(float4*)&sTop[bs][tj][lx0] = make_float4(I[0][0],I[0][1],I[0][2],I[0][3]);
            *(float4*)&sBot[bs][tj][lx0] = make_float4(I[3][0],I[3][1],I[3][2],I[3][3]);

            __syncthreads();

            /* --- post-barrier: only up/dn-dependent fluxes + combines --- */
            float4 upv = (tj > 0)     ? *(float4*)&sBot[bs][tj-1][lx0] : make_float4(0,0,0,0);
            float4 dnv = (tj < NTJ-1) ? *(float4*)&sTop[bs][tj+1][lx0] : make_float4(0,0,0,0);
            float up[4] = {upv.x, upv.y, upv.z, upv.w};
            float dn[4] = {dnv.x, dnv.y, dnv.z, dnv.w};

            float N_[4][4];
            #pragma unroll
            for (int i = 0; i < 4; i++) {
                float f0 = CV[0][i] * (I[0][i] - up[i]);
                float f4 = CV[4][i] * (dn[i]   - I[3][i]);
                N_[0][i] = (I[0][i] - f0)    + F1[i];
                N_[1][i] = (I[1][i] - F1[i]) + F2[i];
                N_[2][i] = (I[2][i] - F2[i]) + F3[i];
                N_[3][i] = (I[3][i] - F3[i]) + f4;
            }
            #pragma unroll
            for (int j = 0; j < 4; j++) {
                I[j][0] = (N_[j][0] - G[j][0]) + G[j][1];
                I[j][1] = (N_[j][1] - G[j][1]) + G[j][2];
                I[j][2] = (N_[j][2] - G[j][2]) + G[j][3];
                I[j][3] = (N_[j][3] - G[j][3]) + G[j][4];
            }
        }

        /* write interior: last phase straight to output, else ping-pong */
        float* __restrict__ wb = (p == NPH-1)
            ? (out_y + (size_t)b*HW)
            : (((p & 1) ? g_I0 : g_I1) + (size_t)b*HW);
        if (xok && lx0 >= HALO && lx0 < TW - HALO) {
            #pragma unroll
            for (int j = 0; j < 4; j++) {
                int ly = ly0 + j;
                int gy = gy0 + j;
                if (ly >= HALO && ly < TH - HALO && gy < H) {
                    *(float4*)(wb + (size_t)gy*W + gx0) =
                        make_float4(I[j][0], I[j][1], I[j][2], I[j][3]);
                }
            }
        }

        if (p < NPH-1) {
            grid_barrier(cta, (unsigned)(p + 1));
            if (!skipReload) {
                const float* __restrict__ rb = ((p & 1) ? g_I0 : g_I1) + (size_t)b*HW;
                #pragma unroll
                for (int j = 0; j < 4; j++) {
                    int gy = gy0 + j;
                    if (xok && gy >= 0 && gy < H) {
                        float4 v = *(const float4*)(rb + (size_t)gy*W + gx0);
                        I[j][0]=v.x; I[j][1]=v.y; I[j][2]=v.z; I[j][3]=v.w;
                    } else {
                        I[j][0]=0.f; I[j][1]=0.f; I[j][2]=0.f; I[j][3]=0.f;
                    }
                }
            }
        }
    }
}

extern "C" void kernel_launch(void* const* d_in, const int* in_sizes, int n_in,
                              void* d_out, int out_size) {
    const float* a0 = (const float*)d_in[0];
    const float* a1 = (const float*)d_in[1];
    const float* guide = a0;
    const float* initial = a1;
    if (n_in >= 2 && in_sizes[0] < in_sizes[1]) { guide = a1; initial = a0; }

    float* out    = (float*)d_out;
    float* out_y  = out;                       /* [BATCH*HW]   */
    float* out_cv = out + BATCH*HW;            /* [NCV]        */
    float* out_ch = out_cv + NCV;              /* [NCH]        */

    k_reset<<<1, 256>>>();
    k_coeff_v<<<(NCV + 255)/256, 256>>>(guide, out_cv);
    k_coeff_h<<<(NCH + 255)/256, 256>>>(guide, out_ch);

    dim3 grid(NBX, NBY, BATCH);
    k_persist<<<grid, NTHREADS>>>(initial, out_y);
}

// round 7
// speedup vs baseline: 2.2482x; 1.0189x over previous
#include <cuda_runtime.h>

#define W 512
#define H 512
#define BATCH 2
#define HW (H*W)
#define NCV (BATCH*(H-1)*W)
#define NCH (BATCH*H*(W-1))
#define L_STEP 0.24f
#define KK 0.0009f   /* 0.03*0.03 */

#define TW 128
#define TH 64
#define HALO 12
#define TSX (TW - 2*HALO)   /* 104 interior width  */
#define TSY (TH - 2*HALO)   /* 40  interior height */
#define NBX 5               /* ceil(512/104) */
#define NBY 13              /* ceil(512/40)  */
#define NTI 32              /* thread-columns (x) == lane id */
#define NTJ 16              /* thread-rows (y)    == warp id */
#define NTHREADS (NTI*NTJ)
#define NCTAS (NBX*NBY*BATCH)   /* 130 <= 148 SMs: co-resident, grid barrier safe */
#define NPH 42                  /* 41*12 + 8 = 500 steps */
#define FLAG_STRIDE 32          /* 128B apart: no same-line write serialization */

/* scratch state (ping-pong) + premultiplied conductances + barrier flags */
__device__ float g_I0[BATCH*HW];
__device__ float g_I1[BATCH*HW];
__device__ float g_cvL[NCV];
__device__ float g_chL[NCH];
__device__ unsigned g_flags[NCTAS*FLAG_STRIDE];

/* ---- conductance kernels: raw g to d_out region, L*g to scratch ---- */
__global__ void k_coeff_v(const float* __restrict__ guide, float* __restrict__ out_cv) {
    int idx = blockIdx.x*blockDim.x + threadIdx.x;
    if (idx >= NCV) return;
    int x = idx % W;
    int y = (idx / W) % (H-1);
    int b = idx / (W*(H-1));
    const float* gb = guide + (size_t)b*3*HW + (size_t)y*W + x;
    float s = 0.f;
    #pragma unroll
    for (int c = 0; c < 3; c++) s += fabsf(gb[(size_t)c*HW + W] - gb[(size_t)c*HW]);
    float m = s * (1.0f/3.0f);
    float g = 1.0f / (1.0f + (m*m)/KK);
    out_cv[idx] = g;
    g_cvL[idx]  = L_STEP * g;
}

__global__ void k_coeff_h(const float* __restrict__ guide, float* __restrict__ out_ch) {
    int idx = blockIdx.x*blockDim.x + threadIdx.x;
    if (idx >= NCH) return;
    int x = idx % (W-1);
    int y = (idx / (W-1)) % H;
    int b = idx / ((W-1)*H);
    const float* gb = guide + (size_t)b*3*HW + (size_t)y*W + x;
    float s = 0.f;
    #pragma unroll
    for (int c = 0; c < 3; c++) s += fabsf(gb[(size_t)c*HW + 1] - gb[(size_t)c*HW]);
    float m = s * (1.0f/3.0f);
    float g = 1.0f / (1.0f + (m*m)/KK);
    out_ch[idx] = g;
    g_chL[idx]  = L_STEP * g;
}

__global__ void k_reset() {
    int idx = blockIdx.x*blockDim.x + threadIdx.x;
    if (idx < NCTAS) g_flags[idx*FLAG_STRIDE] = 0u;
}

__device__ __forceinline__ void flag_store_release(unsigned* p, unsigned v) {
    asm volatile("st.release.gpu.u32 [%0], %1;" :: "l"(p), "r"(v) : "memory");
}
__device__ __forceinline__ unsigned flag_load_acquire(const unsigned* p) {
    unsigned v;
    asm volatile("ld.acquire.gpu.u32 %0, [%1];" : "=r"(v) : "l"(p) : "memory");
    return v;
}

/* software grid barrier: all NCTAS CTAs co-resident (1 CTA/SM, 130<=148). */
__device__ __forceinline__ void grid_barrier(int cta, unsigned target) {
    __syncthreads();
    if (threadIdx.x == 0) flag_store_release(&g_flags[cta*FLAG_STRIDE], target);
    if (threadIdx.x < NCTAS) {
        while (flag_load_acquire(&g_flags[threadIdx.x*FLAG_STRIDE]) < target) {
            __nanosleep(32);
        }
    }
    __syncthreads();
}

/* ---- persistent temporal-blocked diffusion, FMA-fused update ----
 * Per row r: I_r' = fma(c_{r+1}, d_{r+1}, fma(c_r, -d_r, I_r))
 * (diffusion update as two fused FMAs; scheme is a convex combination, so the
 * fusion-induced rounding deltas stay bounded ~1e-5 over 500 steps).
 * Pre-barrier: STS of boundary rows, shuffles, all neighbor diffs that depend
 * only on pre-update I. Post-barrier: up/dn diffs + 64 FFMA combines.
 * Every 12 steps: interior write, grid barrier, reload (halo threads only). */
__global__ void __launch_bounds__(NTHREADS, 1)
k_persist(const float* __restrict__ initial, float* __restrict__ out_y) {
    __shared__ float sTop[2][NTJ][TW];
    __shared__ float sBot[2][NTJ][TW];

    const int tid = threadIdx.x;
    const int ti  = tid & 31;          /* lane id  = x thread-column */
    const int tj  = tid >> 5;          /* warp id  = y thread-row    */
    const int bx = blockIdx.x, by = blockIdx.y, b = blockIdx.z;
    const int cta = bx + NBX*(by + NBY*b);

    const int ox  = bx*TSX - HALO;
    const int oy  = by*TSY - HALO;
    const int lx0 = ti*4, ly0 = tj*4;
    const int gx0 = ox + lx0;
    const int gy0 = oy + ly0;
    const bool xok = (gx0 >= 0) && (gx0 + 4 <= W);
    /* 4x4 fully inside garbage-free tile interior: registers == buffer */
    const bool skipReload = (lx0 >= HALO) && (lx0 + 4 <= TW - HALO) &&
                            (ly0 >= HALO) && (ly0 + 4 <= TH - HALO);

    const float* __restrict__ cvb = g_cvL + (size_t)b*(H-1)*W;
    const float* __restrict__ chb = g_chL + (size_t)b*H*(W-1);

    /* persistent coefficient registers */
    float CV[5][4];   /* rows gy0-1 .. gy0+3 of L*cv */
    #pragma unroll
    for (int jj = 0; jj < 5; jj++) {
        int r = gy0 - 1 + jj;
        if (xok && r >= 0 && r < H-1) {
            float4 v = *(const float4*)(cvb + (size_t)r*W + gx0);
            CV[jj][0]=v.x; CV[jj][1]=v.y; CV[jj][2]=v.z; CV[jj][3]=v.w;
        } else {
            CV[jj][0]=0.f; CV[jj][1]=0.f; CV[jj][2]=0.f; CV[jj][3]=0.f;
        }
    }
    float CH[4][5];   /* cols gx0-1 .. gx0+3 of L*ch */
    #pragma unroll
    for (int j = 0; j < 4; j++) {
        int gy = gy0 + j;
        #pragma unroll
        for (int ii = 0; ii < 5; ii++) {
            int c = gx0 - 1 + ii;
            CH[j][ii] = (gy >= 0 && gy < H && c >= 0 && c < W-1)
                      ? chb[(size_t)gy*(W-1) + c] : 0.f;
        }
    }

    /* initial state straight from input */
    float I[4][4];
    {
        const float* __restrict__ srcb = initial + (size_t)b*HW;
        #pragma unroll
        for (int j = 0; j < 4; j++) {
            int gy = gy0 + j;
            if (xok && gy >= 0 && gy < H) {
                float4 v = *(const float4*)(srcb + (size_t)gy*W + gx0);
                I[j][0]=v.x; I[j][1]=v.y; I[j][2]=v.z; I[j][3]=v.w;
            } else {
                I[j][0]=0.f; I[j][1]=0.f; I[j][2]=0.f; I[j][3]=0.f;
            }
        }
    }

    for (int p = 0; p < NPH; p++) {
        const int nsteps = (p == NPH-1) ? (500 - (NPH-1)*HALO) : HALO;
        for (int s = 0; s < nsteps; s++) {
            const int bs = s & 1;

            /* --- pre-barrier: publish first (minimize barrier skew) --- */
            *(float4*)&sTop[bs][tj][lx0] = make_float4(I[0][0],I[0][1],I[0][2],I[0][3]);
            *(float4*)&sBot[bs][tj][lx0] = make_float4(I[3][0],I[3][1],I[3][2],I[3][3]);

            float lf[4], rt[4];
            #pragma unroll
            for (int j = 0; j < 4; j++) {
                lf[j] = __shfl_up_sync  (0xffffffffu, I[j][3], 1);  /* lane0 garbage -> zero coeff */
                rt[j] = __shfl_down_sync(0xffffffffu, I[j][0], 1);  /* lane31 garbage -> zero coeff */
            }
            /* horizontal diffs dh_c = I_c - I_{c-1} (5 per row) */
            float DH[4][5];
            #pragma unroll
            for (int j = 0; j < 4; j++) {
                DH[j][0] = I[j][0] - lf[j];
                DH[j][1] = I[j][1] - I[j][0];
                DH[j][2] = I[j][2] - I[j][1];
                DH[j][3] = I[j][3] - I[j][2];
                DH[j][4] = rt[j]   - I[j][3];
            }
            /* interior vertical diffs */
            float DV1[4], DV2[4], DV3[4];
            #pragma unroll
            for (int i = 0; i < 4; i++) {
                DV1[i] = I[1][i] - I[0][i];
                DV2[i] = I[2][i] - I[1][i];
                DV3[i] = I[3][i] - I[2][i];
            }

            __syncthreads();

            /* --- post-barrier: up/dn diffs + fused combines --- */
            float4 upv = (tj > 0)     ? *(float4*)&sBot[bs][tj-1][lx0] : make_float4(0,0,0,0);
            float4 dnv = (tj < NTJ-1) ? *(float4*)&sTop[bs][tj+1][lx0] : make_float4(0,0,0,0);
            float up[4] = {upv.x, upv.y, upv.z, upv.w};
            float dn[4] = {dnv.x, dnv.y, dnv.z, dnv.w};

            float N_[4][4];
            #pragma unroll
            for (int i = 0; i < 4; i++) {
                float dv0 = I[0][i] - up[i];
                float dv4 = dn[i]   - I[3][i];
                N_[0][i] = fmaf(CV[1][i], DV1[i], fmaf(CV[0][i], -dv0,    I[0][i]));
                N_[1][i] = fmaf(CV[2][i], DV2[i], fmaf(CV[1][i], -DV1[i], I[1][i]));
                N_[2][i] = fmaf(CV[3][i], DV3[i], fmaf(CV[2][i], -DV2[i], I[2][i]));
                N_[3][i] = fmaf(CV[4][i], dv4,    fmaf(CV[3][i], -DV3[i], I[3][i]));
            }
            #pragma unroll
            for (int j = 0; j < 4; j++) {
                I[j][0] = fmaf(CH[j][1], DH[j][1], fmaf(CH[j][0], -DH[j][0], N_[j][0]));
                I[j][1] = fmaf(CH[j][2], DH[j][2], fmaf(CH[j][1], -DH[j][1], N_[j][1]));
                I[j][2] = fmaf(CH[j][3], DH[j][3], fmaf(CH[j][2], -DH[j][2], N_[j][2]));
                I[j][3] = fmaf(CH[j][4], DH[j][4], fmaf(CH[j][3], -DH[j][3], N_[j][3]));
            }
        }

        /* write interior: last phase straight to output, else ping-pong */
        float* __restrict__ wb = (p == NPH-1)
            ? (out_y + (size_t)b*HW)
            : (((p & 1) ? g_I0 : g_I1) + (size_t)b*HW);
        if (xok && lx0 >= HALO && lx0 < TW - HALO) {
            #pragma unroll
            for (int j = 0; j < 4; j++) {
                int ly = ly0 + j;
                int gy = gy0 + j;
                if (ly >= HALO && ly < TH - HALO && gy < H) {
                    *(float4*)(wb + (size_t)gy*W + gx0) =
                        make_float4(I[j][0], I[j][1], I[j][2], I[j][3]);
                }
            }
        }

        if (p < NPH-1) {
            grid_barrier(cta, (unsigned)(p + 1));
            if (!skipReload) {
                const float* __restrict__ rb = ((p & 1) ? g_I0 : g_I1) + (size_t)b*HW;
                #pragma unroll
                for (int j = 0; j < 4; j++) {
                    int gy = gy0 + j;
                    if (xok && gy >= 0 && gy < H) {
                        float4 v = *(const float4*)(rb + (size_t)gy*W + gx0);
                        I[j][0]=v.x; I[j][1]=v.y; I[j][2]=v.z; I[j][3]=v.w;
                    } else {
                        I[j][0]=0.f; I[j][1]=0.f; I[j][2]=0.f; I[j][3]=0.f;
                    }
                }
            }
        }
    }
}

extern "C" void kernel_launch(void* const* d_in, const int* in_sizes, int n_in,
                              void* d_out, int out_size) {
    const float* a0 = (const float*)d_in[0];
    const float* a1 = (const float*)d_in[1];
    const float* guide = a0;
    const float* initial = a1;
    if (n_in >= 2 && in_sizes[0] < in_sizes[1]) { guide = a1; initial = a0; }

    float* out    = (float*)d_out;
    float* out_y  = out;                       /* [BATCH*HW]   */
    float* out_cv = out + BATCH*HW;            /* [NCV]        */
    float* out_ch = out_cv + NCV;              /* [NCH]        */

    k_reset<<<1, 256>>>();
    k_coeff_v<<<(NCV + 255)/256, 256>>>(guide, out_cv);
    k_coeff_h<<<(NCH + 255)/256, 256>>>(guide, out_ch);

    dim3 grid(NBX, NBY, BATCH);
    k_persist<<<grid, NTHREADS>>>(initial, out_y);
}